// round 4
// baseline (speedup 1.0000x reference)
#include <cuda_runtime.h>
#include <cstdint>
#include <math.h>

// ---------------------------------------------------------------------------
// Attention_3856880632117 — mma.sync bf16 3-term split, cp.async pipelined.
// ptxas target is plain sm_103 (no 'a'): tcgen05 unavailable; tensor cores via
// baseline mma.sync.m16n8k16.bf16 + ldmatrix + cp.async.
//
// All operands are pre-split into bf16 (hi, lo) pairs exactly once:
//   cvt_split: x, Wq, Wk, Wv  -> bf16 hi/lo
//   qkv epilogue writes q, k, vt directly as bf16 hi/lo
//   softmax writes P directly as bf16 hi/lo
// GEMM hot loop: cp.async(16B) -> ldmatrix -> HMMA only.
// C = A*B^T; fp32-accurate via C += Ah*Bh + Ah*Bl + Al*Bh.
// ---------------------------------------------------------------------------

#define NB 4
#define NT 2048
#define NCH 1024
#define NXT (NB * NT)      // 8192

typedef unsigned short u16;

// Scratch (allocation-free rule: __device__ globals).
__device__ u16  g_xh [(size_t)NXT * NCH];    // 16 MB
__device__ u16  g_xl [(size_t)NXT * NCH];
__device__ u16  g_wh [3][(size_t)NCH * NCH]; // Wq,Wk,Wv hi (2 MB each)
__device__ u16  g_wl [3][(size_t)NCH * NCH];
__device__ u16  g_qh [(size_t)NXT * NCH];
__device__ u16  g_ql [(size_t)NXT * NCH];
__device__ u16  g_kh [(size_t)NXT * NCH];
__device__ u16  g_kl [(size_t)NXT * NCH];
__device__ u16  g_vth[(size_t)NCH * NXT];    // V^T: [c][b*T + t]
__device__ u16  g_vtl[(size_t)NCH * NXT];
__device__ float g_s [(size_t)NB * NT * NT]; // 64 MB scores (fp32 for softmax)
__device__ u16  g_sh [(size_t)NB * NT * NT]; // 32 MB probs hi
__device__ u16  g_sl [(size_t)NB * NT * NT]; // 32 MB probs lo

// ---------------- primitives ------------------------------------------------
__device__ __forceinline__ void ldsm4(uint32_t* r, uint32_t addr) {
    asm volatile("ldmatrix.sync.aligned.m8n8.x4.shared.b16 {%0,%1,%2,%3}, [%4];"
                 : "=r"(r[0]), "=r"(r[1]), "=r"(r[2]), "=r"(r[3]) : "r"(addr));
}
__device__ __forceinline__ void mma_bf16(float* c, const uint32_t* a, const uint32_t* b) {
    asm volatile(
        "mma.sync.aligned.m16n8k16.row.col.f32.bf16.bf16.f32 "
        "{%0,%1,%2,%3},{%4,%5,%6,%7},{%8,%9},{%0,%1,%2,%3};"
        : "+f"(c[0]), "+f"(c[1]), "+f"(c[2]), "+f"(c[3])
        : "r"(a[0]), "r"(a[1]), "r"(a[2]), "r"(a[3]), "r"(b[0]), "r"(b[1]));
}
__device__ __forceinline__ uint32_t smem_u32(const void* p) {
    uint32_t a;
    asm("{ .reg .u64 t; cvta.to.shared.u64 t, %1; cvt.u32.u64 %0, t; }"
        : "=r"(a) : "l"(p));
    return a;
}
// pack: result.hi16 = bf16(a), result.lo16 = bf16(b)
__device__ __forceinline__ uint32_t pack2(float a, float b) {
    uint32_t r;
    asm("cvt.rn.bf16x2.f32 %0, %1, %2;" : "=r"(r) : "f"(a), "f"(b));
    return r;
}
__device__ __forceinline__ void cp16(uint32_t dst, const void* src) {
    asm volatile("cp.async.cg.shared.global [%0], [%1], 16;" :: "r"(dst), "l"(src));
}
#define CP_COMMIT() asm volatile("cp.async.commit_group;" ::: "memory")
#define CP_WAIT(n)  asm volatile("cp.async.wait_group %0;" :: "n"(n) : "memory")

// ---------------------------------------------------------------------------
// SMEM: per stage, 4 regions (Ah|Al|Bh|Bl), each 128 rows x 64B payload,
// 80B pitch (conflict-free ldmatrix). 2 stages.
// ---------------------------------------------------------------------------
#define PITCHB     80
#define REGION     10240
#define STAGE_B    40960
#define SMEM_TOTAL (2 * STAGE_B)

// Core: accumulate 128x128 tile over nch K-chunks of 32. acc[4][4][4] per thread.
__device__ __forceinline__ void mma_core(
    const u16* __restrict__ Ah, const u16* __restrict__ Al, int lda,
    const u16* __restrict__ Bh, const u16* __restrict__ Bl, int ldb,
    int nch, float (&acc)[4][4][4])
{
    extern __shared__ char smraw[];
    const uint32_t smu = smem_u32(smraw);

    const int tid  = threadIdx.x;
    const int lane = tid & 31;
    const int wid  = tid >> 5;
    const int wm   = wid >> 2;
    const int wn   = wid & 3;

    const uint32_t aRowByte = (uint32_t)(lane & 15) * PITCHB + (uint32_t)(lane >> 4) * 16;
    const uint32_t bRowByte = (uint32_t)(((lane >> 4) << 3) + (lane & 7)) * PITCHB
                            + (uint32_t)((lane >> 3) & 1) * 16;

    // per-thread load coords: 2 iterations x 4 regions, 16B each
    const int row0 = tid >> 2;          // 0..63
    const int seg  = tid & 3;           // 16B segment within 64B row payload

    auto load_chunk = [&](int kt, int buf) {
        const int kb = kt * 32;
        const uint32_t sb = smu + (uint32_t)buf * STAGE_B;
        #pragma unroll
        for (int i = 0; i < 2; ++i) {
            const int row = row0 + i * 64;
            const uint32_t d = sb + (uint32_t)row * PITCHB + (uint32_t)seg * 16;
            const size_t ao = (size_t)row * lda + kb + seg * 8;
            const size_t bo = (size_t)row * ldb + kb + seg * 8;
            cp16(d,              Ah + ao);
            cp16(d + REGION,     Al + ao);
            cp16(d + 2 * REGION, Bh + bo);
            cp16(d + 3 * REGION, Bl + bo);
        }
        CP_COMMIT();
    };

    auto mma_chunk = [&](int buf) {
        const uint32_t sbase = smu + (uint32_t)buf * STAGE_B;
        #pragma unroll
        for (int sk = 0; sk < 2; ++sk) {
            uint32_t ah[4][4], al[4][4], bh[4][2], bl[4][2];
            const uint32_t aBase = sbase + (uint32_t)(wm * 64) * PITCHB + aRowByte
                                 + (uint32_t)sk * 32;
            #pragma unroll
            for (int mf = 0; mf < 4; ++mf) {
                ldsm4(ah[mf], aBase + (uint32_t)mf * (16 * PITCHB));
                ldsm4(al[mf], aBase + (uint32_t)mf * (16 * PITCHB) + REGION);
            }
            const uint32_t bBase = sbase + 2 * REGION + (uint32_t)(wn * 32) * PITCHB
                                 + bRowByte + (uint32_t)sk * 32;
            #pragma unroll
            for (int p = 0; p < 2; ++p) {
                uint32_t t[4];
                ldsm4(t, bBase + (uint32_t)p * (16 * PITCHB));
                bh[2 * p][0] = t[0]; bh[2 * p][1] = t[1];
                bh[2 * p + 1][0] = t[2]; bh[2 * p + 1][1] = t[3];
                ldsm4(t, bBase + (uint32_t)p * (16 * PITCHB) + REGION);
                bl[2 * p][0] = t[0]; bl[2 * p][1] = t[1];
                bl[2 * p + 1][0] = t[2]; bl[2 * p + 1][1] = t[3];
            }
            #pragma unroll
            for (int mf = 0; mf < 4; ++mf)
                #pragma unroll
                for (int nf = 0; nf < 4; ++nf)
                    mma_bf16(acc[mf][nf], ah[mf], bh[nf]);
            #pragma unroll
            for (int mf = 0; mf < 4; ++mf)
                #pragma unroll
                for (int nf = 0; nf < 4; ++nf)
                    mma_bf16(acc[mf][nf], ah[mf], bl[nf]);
            #pragma unroll
            for (int mf = 0; mf < 4; ++mf)
                #pragma unroll
                for (int nf = 0; nf < 4; ++nf)
                    mma_bf16(acc[mf][nf], al[mf], bh[nf]);
        }
    };

    load_chunk(0, 0);
    load_chunk(1, 1);
    for (int kt = 0; kt < nch; ++kt) {
        if (kt == nch - 1) { CP_WAIT(0); } else { CP_WAIT(1); }
        __syncthreads();
        mma_chunk(kt & 1);
        __syncthreads();
        if (kt + 2 < nch) load_chunk(kt + 2, kt & 1);
    }
}

// fp32 epilogue: C[row][col..] float2 pairs
__device__ __forceinline__ void epi_f32(float (&acc)[4][4][4],
                                        float* __restrict__ Ct, int ldc)
{
    const int lane = threadIdx.x & 31, wid = threadIdx.x >> 5;
    const int wm = wid >> 2, wn = wid & 3;
    #pragma unroll
    for (int mf = 0; mf < 4; ++mf)
        #pragma unroll
        for (int nf = 0; nf < 4; ++nf) {
            int row = wm * 64 + mf * 16 + (lane >> 2);
            int col = wn * 32 + nf * 8 + (lane & 3) * 2;
            *reinterpret_cast<float2*>(Ct + (size_t)row * ldc + col) =
                make_float2(acc[mf][nf][0], acc[mf][nf][1]);
            *reinterpret_cast<float2*>(Ct + (size_t)(row + 8) * ldc + col) =
                make_float2(acc[mf][nf][2], acc[mf][nf][3]);
        }
}

// bf16 hi/lo epilogue: write packed bf16x2 to Chi/Clo
__device__ __forceinline__ void epi_bf16(float (&acc)[4][4][4],
                                         u16* __restrict__ Chi,
                                         u16* __restrict__ Clo, int ldc)
{
    const int lane = threadIdx.x & 31, wid = threadIdx.x >> 5;
    const int wm = wid >> 2, wn = wid & 3;
    #pragma unroll
    for (int mf = 0; mf < 4; ++mf)
        #pragma unroll
        for (int nf = 0; nf < 4; ++nf) {
            int row = wm * 64 + mf * 16 + (lane >> 2);
            int col = wn * 32 + nf * 8 + (lane & 3) * 2;
            float c0 = acc[mf][nf][0], c1 = acc[mf][nf][1];
            float c2 = acc[mf][nf][2], c3 = acc[mf][nf][3];
            uint32_t h01 = pack2(c1, c0);
            uint32_t h23 = pack2(c3, c2);
            float f0 = __uint_as_float(h01 << 16);
            float f1 = __uint_as_float(h01 & 0xFFFF0000u);
            float f2 = __uint_as_float(h23 << 16);
            float f3 = __uint_as_float(h23 & 0xFFFF0000u);
            uint32_t l01 = pack2(c1 - f1, c0 - f0);
            uint32_t l23 = pack2(c3 - f3, c2 - f2);
            *reinterpret_cast<uint32_t*>(Chi + (size_t)row * ldc + col) = h01;
            *reinterpret_cast<uint32_t*>(Clo + (size_t)row * ldc + col) = l01;
            *reinterpret_cast<uint32_t*>(Chi + (size_t)(row + 8) * ldc + col) = h23;
            *reinterpret_cast<uint32_t*>(Clo + (size_t)(row + 8) * ldc + col) = l23;
        }
}

// ---------------------------------------------------------------------------
// cvt_split: fp32 -> (bf16 hi, bf16 lo), float4 per thread, grid-stride.
__global__ __launch_bounds__(256)
void cvt_split(const float* __restrict__ src, u16* __restrict__ hi,
               u16* __restrict__ lo, int n4)
{
    for (int i = blockIdx.x * 256 + threadIdx.x; i < n4; i += gridDim.x * 256) {
        float4 v = reinterpret_cast<const float4*>(src)[i];
        uint32_t h01 = pack2(v.y, v.x);
        uint32_t h23 = pack2(v.w, v.z);
        float fx = __uint_as_float(h01 << 16);
        float fy = __uint_as_float(h01 & 0xFFFF0000u);
        float fz = __uint_as_float(h23 << 16);
        float fw = __uint_as_float(h23 & 0xFFFF0000u);
        uint32_t l01 = pack2(v.y - fy, v.x - fx);
        uint32_t l23 = pack2(v.w - fw, v.z - fz);
        reinterpret_cast<uint2*>(hi)[i] = make_uint2(h01, h23);
        reinterpret_cast<uint2*>(lo)[i] = make_uint2(l01, l23);
    }
}

// Stage 1: QKV. grid=(64,8,3). z<2: bx = m-tile of 8192, by = n-tile of 1024.
// z==2: vt = Wv x^T -> by = m-tile over rows c (1024), bx = n-tile over t (8192).
__global__ __launch_bounds__(256, 2)
void qkv_mma(int dummy)
{
    const int bx = blockIdx.x, by = blockIdx.y, z = blockIdx.z;
    float acc[4][4][4];
    #pragma unroll
    for (int a = 0; a < 4; ++a)
        #pragma unroll
        for (int b = 0; b < 4; ++b)
            #pragma unroll
            for (int c = 0; c < 4; ++c) acc[a][b][c] = 0.0f;

    if (z < 2) {
        mma_core(g_xh + (size_t)bx * 128 * NCH, g_xl + (size_t)bx * 128 * NCH, NCH,
                 g_wh[z] + (size_t)by * 128 * NCH, g_wl[z] + (size_t)by * 128 * NCH, NCH,
                 NCH / 32, acc);
        u16* oh = (z == 0) ? g_qh : g_kh;
        u16* ol = (z == 0) ? g_ql : g_kl;
        epi_bf16(acc, oh + (size_t)bx * 128 * NCH + by * 128,
                      ol + (size_t)bx * 128 * NCH + by * 128, NCH);
    } else {
        mma_core(g_wh[2] + (size_t)by * 128 * NCH, g_wl[2] + (size_t)by * 128 * NCH, NCH,
                 g_xh + (size_t)bx * 128 * NCH, g_xl + (size_t)bx * 128 * NCH, NCH,
                 NCH / 32, acc);
        epi_bf16(acc, g_vth + (size_t)by * 128 * NXT + bx * 128,
                      g_vtl + (size_t)by * 128 * NXT + bx * 128, NXT);
    }
}

// Stage 2: S = Q K^T, lower-triangular tiles. grid=(16,16,NB)
__global__ __launch_bounds__(256, 2)
void qk_mma(int dummy)
{
    if (blockIdx.x > blockIdx.y) return;
    const int b = blockIdx.z;
    const size_t qo = (size_t)b * NT * NCH + (size_t)blockIdx.y * 128 * NCH;
    const size_t ko = (size_t)b * NT * NCH + (size_t)blockIdx.x * 128 * NCH;
    float acc[4][4][4];
    #pragma unroll
    for (int a = 0; a < 4; ++a)
        #pragma unroll
        for (int bb = 0; bb < 4; ++bb)
            #pragma unroll
            for (int c = 0; c < 4; ++c) acc[a][bb][c] = 0.0f;
    mma_core(g_qh + qo, g_ql + qo, NCH, g_kh + ko, g_kl + ko, NCH, NCH / 32, acc);
    epi_f32(acc, g_s + (size_t)b * NT * NT + (size_t)blockIdx.y * 128 * NT
                     + blockIdx.x * 128, NT);
}

// Stage 3: causal softmax (scale fused); writes P as bf16 hi/lo, zero-padded.
__global__ __launch_bounds__(256)
void softmax_causal(float scale)
{
    const int i = blockIdx.x;
    const size_t ro = ((size_t)blockIdx.y * NT + i) * NT;
    float* row = g_s + ro;
    const int len = i + 1;
    const int tid = threadIdx.x;
    const int lane = tid & 31, warp = tid >> 5;

    __shared__ float sh[8];
    __shared__ float s_bcast;

    float m = -INFINITY;
    for (int j = tid; j < len; j += 256) m = fmaxf(m, row[j]);
    #pragma unroll
    for (int o = 16; o > 0; o >>= 1) m = fmaxf(m, __shfl_xor_sync(0xffffffffu, m, o));
    if (lane == 0) sh[warp] = m;
    __syncthreads();
    if (tid < 32) {
        float v = (lane < 8) ? sh[lane] : -INFINITY;
        #pragma unroll
        for (int o = 4; o > 0; o >>= 1) v = fmaxf(v, __shfl_xor_sync(0xffffffffu, v, o));
        if (lane == 0) s_bcast = v;
    }
    __syncthreads();
    m = s_bcast;
    __syncthreads();

    float s = 0.0f;
    for (int j = tid; j < len; j += 256) {
        float e = __expf((row[j] - m) * scale);
        row[j] = e;
        s += e;
    }
    #pragma unroll
    for (int o = 16; o > 0; o >>= 1) s += __shfl_xor_sync(0xffffffffu, s, o);
    if (lane == 0) sh[warp] = s;
    __syncthreads();
    if (tid < 32) {
        float v = (lane < 8) ? sh[lane] : 0.0f;
        #pragma unroll
        for (int o = 4; o > 0; o >>= 1) v += __shfl_xor_sync(0xffffffffu, v, o);
        if (lane == 0) s_bcast = v;
    }
    __syncthreads();
    const float inv = 1.0f / s_bcast;

    const int jend = ((i >> 7) + 1) << 7;   // pad to 128 boundary
    for (int j2 = tid * 2; j2 < jend; j2 += 512) {
        float p0 = (j2     < len) ? row[j2]     * inv : 0.0f;
        float p1 = (j2 + 1 < len) ? row[j2 + 1] * inv : 0.0f;
        uint32_t h = pack2(p1, p0);
        float f0 = __uint_as_float(h << 16);
        float f1 = __uint_as_float(h & 0xFFFF0000u);
        uint32_t l = pack2(p1 - f1, p0 - f0);
        *reinterpret_cast<uint32_t*>(g_sh + ro + j2) = h;
        *reinterpret_cast<uint32_t*>(g_sl + ro + j2) = l;
    }
}

// Stage 4: out = P vt^T, k-extent clipped. grid=(8,16,NB)
__global__ __launch_bounds__(256, 2)
void pv_mma(float* __restrict__ out)
{
    const int b = blockIdx.z, by = blockIdx.y, bx = blockIdx.x;
    const size_t so = (size_t)b * NT * NT + (size_t)by * 128 * NT;
    const size_t vo = (size_t)bx * 128 * NXT + (size_t)b * NT;
    float acc[4][4][4];
    #pragma unroll
    for (int a = 0; a < 4; ++a)
        #pragma unroll
        for (int bb = 0; bb < 4; ++bb)
            #pragma unroll
            for (int c = 0; c < 4; ++c) acc[a][bb][c] = 0.0f;
    mma_core(g_sh + so, g_sl + so, NT, g_vth + vo, g_vtl + vo, NXT,
             (by + 1) * 4, acc);
    epi_f32(acc, out + (size_t)b * NT * NCH + (size_t)by * 128 * NCH + bx * 128, NCH);
}

extern "C" void kernel_launch(void* const* d_in, const int* in_sizes, int n_in,
                              void* d_out, int out_size)
{
    const float* x  = (const float*)d_in[0];
    const float* Wq = (const float*)d_in[1];
    const float* Wk = (const float*)d_in[2];
    const float* Wv = (const float*)d_in[3];
    float* out = (float*)d_out;

    static bool attr_done = false;
    if (!attr_done) {
        cudaFuncSetAttribute(qkv_mma, cudaFuncAttributeMaxDynamicSharedMemorySize, SMEM_TOTAL);
        cudaFuncSetAttribute(qk_mma,  cudaFuncAttributeMaxDynamicSharedMemorySize, SMEM_TOTAL);
        cudaFuncSetAttribute(pv_mma,  cudaFuncAttributeMaxDynamicSharedMemorySize, SMEM_TOTAL);
        attr_done = true;
    }

    u16* wh0; u16* wl0;
    cudaGetSymbolAddress((void**)&wh0, g_wh);
    cudaGetSymbolAddress((void**)&wl0, g_wl);
    u16* xh; u16* xl;
    cudaGetSymbolAddress((void**)&xh, g_xh);
    cudaGetSymbolAddress((void**)&xl, g_xl);

    dim3 blk(256);
    cvt_split<<<2048, blk>>>(x,  xh, xl, (NXT * NCH) / 4);
    cvt_split<<<512,  blk>>>(Wq, wh0,                    wl0,                    (NCH * NCH) / 4);
    cvt_split<<<512,  blk>>>(Wk, wh0 + (size_t)NCH*NCH,  wl0 + (size_t)NCH*NCH,  (NCH * NCH) / 4);
    cvt_split<<<512,  blk>>>(Wv, wh0 + (size_t)2*NCH*NCH,wl0 + (size_t)2*NCH*NCH,(NCH * NCH) / 4);

    qkv_mma<<<dim3(64, 8, 3), blk, SMEM_TOTAL>>>(0);
    qk_mma<<<dim3(16, 16, NB), blk, SMEM_TOTAL>>>(0);
    softmax_causal<<<dim3(NT, NB), blk>>>(1.0f / 32.0f);   // 1024^-0.5
    pv_mma<<<dim3(8, 16, NB), blk, SMEM_TOTAL>>>(out);
}

// round 5
// speedup vs baseline: 1.0367x; 1.0367x over previous
#include <cuda_runtime.h>
#include <cstdint>
#include <math.h>

// ---------------------------------------------------------------------------
// Attention_3856880632117 — mma.sync bf16 3-term split, cp.async 3-stage ring.
// ptxas target is plain sm_103 (no 'a'): tcgen05 unavailable; tensor cores via
// baseline mma.sync.m16n8k16.bf16 + ldmatrix + cp.async.
//
// All operands pre-split into bf16 (hi, lo) exactly once:
//   cvt_split: x, Wq, Wk, Wv -> hi/lo; qkv epilogue emits q,k,vt hi/lo;
//   softmax emits P hi/lo. GEMM hot loop: cp.async -> ldmatrix -> HMMA only.
// C = A*B^T; fp32 accuracy via C += Ah*Bh + Ah*Bl + Al*Bh.
// Pipeline: 3 SMEM stages, ONE __syncthreads per K-chunk, prefetch distance 2.
// ---------------------------------------------------------------------------

#define NB 4
#define NT 2048
#define NCH 1024
#define NXT (NB * NT)      // 8192

typedef unsigned short u16;

// Scratch (allocation-free rule: __device__ globals).
__device__ u16  g_xh [(size_t)NXT * NCH];
__device__ u16  g_xl [(size_t)NXT * NCH];
__device__ u16  g_wh [3][(size_t)NCH * NCH];
__device__ u16  g_wl [3][(size_t)NCH * NCH];
__device__ u16  g_qh [(size_t)NXT * NCH];
__device__ u16  g_ql [(size_t)NXT * NCH];
__device__ u16  g_kh [(size_t)NXT * NCH];
__device__ u16  g_kl [(size_t)NXT * NCH];
__device__ u16  g_vth[(size_t)NCH * NXT];    // V^T: [c][b*T + t]
__device__ u16  g_vtl[(size_t)NCH * NXT];
__device__ float g_s [(size_t)NB * NT * NT]; // scores (fp32 for softmax)
__device__ u16  g_sh [(size_t)NB * NT * NT]; // probs hi
__device__ u16  g_sl [(size_t)NB * NT * NT]; // probs lo

// ---------------- primitives ------------------------------------------------
__device__ __forceinline__ void ldsm4(uint32_t* r, uint32_t addr) {
    asm volatile("ldmatrix.sync.aligned.m8n8.x4.shared.b16 {%0,%1,%2,%3}, [%4];"
                 : "=r"(r[0]), "=r"(r[1]), "=r"(r[2]), "=r"(r[3]) : "r"(addr));
}
__device__ __forceinline__ void mma_bf16(float* c, const uint32_t* a, const uint32_t* b) {
    asm volatile(
        "mma.sync.aligned.m16n8k16.row.col.f32.bf16.bf16.f32 "
        "{%0,%1,%2,%3},{%4,%5,%6,%7},{%8,%9},{%0,%1,%2,%3};"
        : "+f"(c[0]), "+f"(c[1]), "+f"(c[2]), "+f"(c[3])
        : "r"(a[0]), "r"(a[1]), "r"(a[2]), "r"(a[3]), "r"(b[0]), "r"(b[1]));
}
__device__ __forceinline__ uint32_t smem_u32(const void* p) {
    uint32_t a;
    asm("{ .reg .u64 t; cvta.to.shared.u64 t, %1; cvt.u32.u64 %0, t; }"
        : "=r"(a) : "l"(p));
    return a;
}
__device__ __forceinline__ uint32_t pack2(float a, float b) {
    uint32_t r;
    asm("cvt.rn.bf16x2.f32 %0, %1, %2;" : "=r"(r) : "f"(a), "f"(b));
    return r;
}
__device__ __forceinline__ void cp16(uint32_t dst, const void* src) {
    asm volatile("cp.async.cg.shared.global [%0], [%1], 16;" :: "r"(dst), "l"(src));
}
#define CP_COMMIT() asm volatile("cp.async.commit_group;" ::: "memory")
#define CP_WAIT(n)  asm volatile("cp.async.wait_group %0;" :: "n"(n) : "memory")

// ---------------------------------------------------------------------------
// SMEM: per stage, 4 regions (Ah|Al|Bh|Bl), 128 rows x 64B payload, 80B pitch
// (conflict-free ldmatrix). 3 stages.
// ---------------------------------------------------------------------------
#define PITCHB     80
#define REGION     10240
#define STAGE_B    40960
#define NSTAGE     3
#define SMEM_TOTAL (NSTAGE * STAGE_B)

// Core: accumulate 128x128 tile over nch K-chunks of 32.
__device__ __forceinline__ void mma_core(
    const u16* __restrict__ Ah, const u16* __restrict__ Al, int lda,
    const u16* __restrict__ Bh, const u16* __restrict__ Bl, int ldb,
    int nch, float (&acc)[4][4][4])
{
    extern __shared__ char smraw[];
    const uint32_t smu = smem_u32(smraw);

    const int tid  = threadIdx.x;
    const int lane = tid & 31;
    const int wid  = tid >> 5;
    const int wm   = wid >> 2;
    const int wn   = wid & 3;

    const uint32_t aRowByte = (uint32_t)(lane & 15) * PITCHB + (uint32_t)(lane >> 4) * 16;
    const uint32_t bRowByte = (uint32_t)(((lane >> 4) << 3) + (lane & 7)) * PITCHB
                            + (uint32_t)((lane >> 3) & 1) * 16;

    const int row0 = tid >> 2;          // 0..63
    const int seg  = tid & 3;           // 16B segment within 64B payload

    auto load_chunk = [&](int kt, int buf) {
        const int kb = kt * 32;
        const uint32_t sb = smu + (uint32_t)buf * STAGE_B;
        #pragma unroll
        for (int i = 0; i < 2; ++i) {
            const int row = row0 + i * 64;
            const uint32_t d = sb + (uint32_t)row * PITCHB + (uint32_t)seg * 16;
            const size_t ao = (size_t)row * lda + kb + seg * 8;
            const size_t bo = (size_t)row * ldb + kb + seg * 8;
            cp16(d,              Ah + ao);
            cp16(d + REGION,     Al + ao);
            cp16(d + 2 * REGION, Bh + bo);
            cp16(d + 3 * REGION, Bl + bo);
        }
        CP_COMMIT();
    };

    auto mma_chunk = [&](int buf) {
        const uint32_t sbase = smu + (uint32_t)buf * STAGE_B;
        #pragma unroll
        for (int sk = 0; sk < 2; ++sk) {
            uint32_t ah[4][4], al[4][4], bh[4][2], bl[4][2];
            const uint32_t aBase = sbase + (uint32_t)(wm * 64) * PITCHB + aRowByte
                                 + (uint32_t)sk * 32;
            #pragma unroll
            for (int mf = 0; mf < 4; ++mf) {
                ldsm4(ah[mf], aBase + (uint32_t)mf * (16 * PITCHB));
                ldsm4(al[mf], aBase + (uint32_t)mf * (16 * PITCHB) + REGION);
            }
            const uint32_t bBase = sbase + 2 * REGION + (uint32_t)(wn * 32) * PITCHB
                                 + bRowByte + (uint32_t)sk * 32;
            #pragma unroll
            for (int p = 0; p < 2; ++p) {
                uint32_t t[4];
                ldsm4(t, bBase + (uint32_t)p * (16 * PITCHB));
                bh[2 * p][0] = t[0]; bh[2 * p][1] = t[1];
                bh[2 * p + 1][0] = t[2]; bh[2 * p + 1][1] = t[3];
                ldsm4(t, bBase + (uint32_t)p * (16 * PITCHB) + REGION);
                bl[2 * p][0] = t[0]; bl[2 * p][1] = t[1];
                bl[2 * p + 1][0] = t[2]; bl[2 * p + 1][1] = t[3];
            }
            #pragma unroll
            for (int mf = 0; mf < 4; ++mf)
                #pragma unroll
                for (int nf = 0; nf < 4; ++nf)
                    mma_bf16(acc[mf][nf], ah[mf], bh[nf]);
            #pragma unroll
            for (int mf = 0; mf < 4; ++mf)
                #pragma unroll
                for (int nf = 0; nf < 4; ++nf)
                    mma_bf16(acc[mf][nf], ah[mf], bl[nf]);
            #pragma unroll
            for (int mf = 0; mf < 4; ++mf)
                #pragma unroll
                for (int nf = 0; nf < 4; ++nf)
                    mma_bf16(acc[mf][nf], al[mf], bh[nf]);
        }
    };

    // 3-stage ring, one barrier per chunk, prefetch distance 2.
    load_chunk(0, 0);
    if (nch > 1) load_chunk(1, 1);
    for (int kt = 0; kt < nch; ++kt) {
        if (kt + 1 < nch) { CP_WAIT(1); } else { CP_WAIT(0); }
        __syncthreads();                 // chunk kt visible to all warps;
                                         // all warps past mma(kt-1)
        mma_chunk(kt % NSTAGE);
        if (kt + 2 < nch)                // buf (kt+2)%3 was consumed at kt-1
            load_chunk(kt + 2, (kt + 2) % NSTAGE);
    }
}

// fp32 epilogue
__device__ __forceinline__ void epi_f32(float (&acc)[4][4][4],
                                        float* __restrict__ Ct, int ldc)
{
    const int lane = threadIdx.x & 31, wid = threadIdx.x >> 5;
    const int wm = wid >> 2, wn = wid & 3;
    #pragma unroll
    for (int mf = 0; mf < 4; ++mf)
        #pragma unroll
        for (int nf = 0; nf < 4; ++nf) {
            int row = wm * 64 + mf * 16 + (lane >> 2);
            int col = wn * 32 + nf * 8 + (lane & 3) * 2;
            *reinterpret_cast<float2*>(Ct + (size_t)row * ldc + col) =
                make_float2(acc[mf][nf][0], acc[mf][nf][1]);
            *reinterpret_cast<float2*>(Ct + (size_t)(row + 8) * ldc + col) =
                make_float2(acc[mf][nf][2], acc[mf][nf][3]);
        }
}

// bf16 hi/lo epilogue
__device__ __forceinline__ void epi_bf16(float (&acc)[4][4][4],
                                         u16* __restrict__ Chi,
                                         u16* __restrict__ Clo, int ldc)
{
    const int lane = threadIdx.x & 31, wid = threadIdx.x >> 5;
    const int wm = wid >> 2, wn = wid & 3;
    #pragma unroll
    for (int mf = 0; mf < 4; ++mf)
        #pragma unroll
        for (int nf = 0; nf < 4; ++nf) {
            int row = wm * 64 + mf * 16 + (lane >> 2);
            int col = wn * 32 + nf * 8 + (lane & 3) * 2;
            float c0 = acc[mf][nf][0], c1 = acc[mf][nf][1];
            float c2 = acc[mf][nf][2], c3 = acc[mf][nf][3];
            uint32_t h01 = pack2(c1, c0);
            uint32_t h23 = pack2(c3, c2);
            float f0 = __uint_as_float(h01 << 16);
            float f1 = __uint_as_float(h01 & 0xFFFF0000u);
            float f2 = __uint_as_float(h23 << 16);
            float f3 = __uint_as_float(h23 & 0xFFFF0000u);
            uint32_t l01 = pack2(c1 - f1, c0 - f0);
            uint32_t l23 = pack2(c3 - f3, c2 - f2);
            *reinterpret_cast<uint32_t*>(Chi + (size_t)row * ldc + col) = h01;
            *reinterpret_cast<uint32_t*>(Clo + (size_t)row * ldc + col) = l01;
            *reinterpret_cast<uint32_t*>(Chi + (size_t)(row + 8) * ldc + col) = h23;
            *reinterpret_cast<uint32_t*>(Clo + (size_t)(row + 8) * ldc + col) = l23;
        }
}

// cvt_split: fp32 -> (bf16 hi, bf16 lo)
__global__ __launch_bounds__(256)
void cvt_split(const float* __restrict__ src, u16* __restrict__ hi,
               u16* __restrict__ lo, int n4)
{
    for (int i = blockIdx.x * 256 + threadIdx.x; i < n4; i += gridDim.x * 256) {
        float4 v = reinterpret_cast<const float4*>(src)[i];
        uint32_t h01 = pack2(v.y, v.x);
        uint32_t h23 = pack2(v.w, v.z);
        float fx = __uint_as_float(h01 << 16);
        float fy = __uint_as_float(h01 & 0xFFFF0000u);
        float fz = __uint_as_float(h23 << 16);
        float fw = __uint_as_float(h23 & 0xFFFF0000u);
        uint32_t l01 = pack2(v.y - fy, v.x - fx);
        uint32_t l23 = pack2(v.w - fw, v.z - fz);
        reinterpret_cast<uint2*>(hi)[i] = make_uint2(h01, h23);
        reinterpret_cast<uint2*>(lo)[i] = make_uint2(l01, l23);
    }
}

// Stage 1: QKV. grid=(64,8,3).
__global__ __launch_bounds__(256)
void qkv_mma(int dummy)
{
    const int bx = blockIdx.x, by = blockIdx.y, z = blockIdx.z;
    float acc[4][4][4];
    #pragma unroll
    for (int a = 0; a < 4; ++a)
        #pragma unroll
        for (int b = 0; b < 4; ++b)
            #pragma unroll
            for (int c = 0; c < 4; ++c) acc[a][b][c] = 0.0f;

    if (z < 2) {
        mma_core(g_xh + (size_t)bx * 128 * NCH, g_xl + (size_t)bx * 128 * NCH, NCH,
                 g_wh[z] + (size_t)by * 128 * NCH, g_wl[z] + (size_t)by * 128 * NCH, NCH,
                 NCH / 32, acc);
        u16* oh = (z == 0) ? g_qh : g_kh;
        u16* ol = (z == 0) ? g_ql : g_kl;
        epi_bf16(acc, oh + (size_t)bx * 128 * NCH + by * 128,
                      ol + (size_t)bx * 128 * NCH + by * 128, NCH);
    } else {
        mma_core(g_wh[2] + (size_t)by * 128 * NCH, g_wl[2] + (size_t)by * 128 * NCH, NCH,
                 g_xh + (size_t)bx * 128 * NCH, g_xl + (size_t)bx * 128 * NCH, NCH,
                 NCH / 32, acc);
        epi_bf16(acc, g_vth + (size_t)by * 128 * NXT + bx * 128,
                      g_vtl + (size_t)by * 128 * NXT + bx * 128, NXT);
    }
}

// Stage 2: S = Q K^T, lower-triangular tiles. grid=(16,16,NB)
__global__ __launch_bounds__(256)
void qk_mma(int dummy)
{
    if (blockIdx.x > blockIdx.y) return;
    const int b = blockIdx.z;
    const size_t qo = (size_t)b * NT * NCH + (size_t)blockIdx.y * 128 * NCH;
    const size_t ko = (size_t)b * NT * NCH + (size_t)blockIdx.x * 128 * NCH;
    float acc[4][4][4];
    #pragma unroll
    for (int a = 0; a < 4; ++a)
        #pragma unroll
        for (int bb = 0; bb < 4; ++bb)
            #pragma unroll
            for (int c = 0; c < 4; ++c) acc[a][bb][c] = 0.0f;
    mma_core(g_qh + qo, g_ql + qo, NCH, g_kh + ko, g_kl + ko, NCH, NCH / 32, acc);
    epi_f32(acc, g_s + (size_t)b * NT * NT + (size_t)blockIdx.y * 128 * NT
                     + blockIdx.x * 128, NT);
}

// Stage 3: causal softmax (scale fused); writes P as bf16 hi/lo, zero-padded.
__global__ __launch_bounds__(256)
void softmax_causal(float scale)
{
    const int i = blockIdx.x;
    const size_t ro = ((size_t)blockIdx.y * NT + i) * NT;
    float* row = g_s + ro;
    const int len = i + 1;
    const int tid = threadIdx.x;
    const int lane = tid & 31, warp = tid >> 5;

    __shared__ float sh[8];
    __shared__ float s_bcast;

    float m = -INFINITY;
    for (int j = tid; j < len; j += 256) m = fmaxf(m, row[j]);
    #pragma unroll
    for (int o = 16; o > 0; o >>= 1) m = fmaxf(m, __shfl_xor_sync(0xffffffffu, m, o));
    if (lane == 0) sh[warp] = m;
    __syncthreads();
    if (tid < 32) {
        float v = (lane < 8) ? sh[lane] : -INFINITY;
        #pragma unroll
        for (int o = 4; o > 0; o >>= 1) v = fmaxf(v, __shfl_xor_sync(0xffffffffu, v, o));
        if (lane == 0) s_bcast = v;
    }
    __syncthreads();
    m = s_bcast;
    __syncthreads();

    float s = 0.0f;
    for (int j = tid; j < len; j += 256) {
        float e = __expf((row[j] - m) * scale);
        row[j] = e;
        s += e;
    }
    #pragma unroll
    for (int o = 16; o > 0; o >>= 1) s += __shfl_xor_sync(0xffffffffu, s, o);
    if (lane == 0) sh[warp] = s;
    __syncthreads();
    if (tid < 32) {
        float v = (lane < 8) ? sh[lane] : 0.0f;
        #pragma unroll
        for (int o = 4; o > 0; o >>= 1) v += __shfl_xor_sync(0xffffffffu, v, o);
        if (lane == 0) s_bcast = v;
    }
    __syncthreads();
    const float inv = 1.0f / s_bcast;

    const int jend = ((i >> 7) + 1) << 7;   // pad to 128 boundary
    for (int j2 = tid * 2; j2 < jend; j2 += 512) {
        float p0 = (j2     < len) ? row[j2]     * inv : 0.0f;
        float p1 = (j2 + 1 < len) ? row[j2 + 1] * inv : 0.0f;
        uint32_t h = pack2(p1, p0);
        float f0 = __uint_as_float(h << 16);
        float f1 = __uint_as_float(h & 0xFFFF0000u);
        uint32_t l = pack2(p1 - f1, p0 - f0);
        *reinterpret_cast<uint32_t*>(g_sh + ro + j2) = h;
        *reinterpret_cast<uint32_t*>(g_sl + ro + j2) = l;
    }
}

// Stage 4: out = P vt^T, k-extent clipped. grid=(8,16,NB)
__global__ __launch_bounds__(256)
void pv_mma(float* __restrict__ out)
{
    const int b = blockIdx.z, by = blockIdx.y, bx = blockIdx.x;
    const size_t so = (size_t)b * NT * NT + (size_t)by * 128 * NT;
    const size_t vo = (size_t)bx * 128 * NXT + (size_t)b * NT;
    float acc[4][4][4];
    #pragma unroll
    for (int a = 0; a < 4; ++a)
        #pragma unroll
        for (int bb = 0; bb < 4; ++bb)
            #pragma unroll
            for (int c = 0; c < 4; ++c) acc[a][bb][c] = 0.0f;
    mma_core(g_sh + so, g_sl + so, NT, g_vth + vo, g_vtl + vo, NXT,
             (by + 1) * 4, acc);
    epi_f32(acc, out + (size_t)b * NT * NCH + (size_t)by * 128 * NCH + bx * 128, NCH);
}

extern "C" void kernel_launch(void* const* d_in, const int* in_sizes, int n_in,
                              void* d_out, int out_size)
{
    const float* x  = (const float*)d_in[0];
    const float* Wq = (const float*)d_in[1];
    const float* Wk = (const float*)d_in[2];
    const float* Wv = (const float*)d_in[3];
    float* out = (float*)d_out;

    static bool attr_done = false;
    if (!attr_done) {
        cudaFuncSetAttribute(qkv_mma, cudaFuncAttributeMaxDynamicSharedMemorySize, SMEM_TOTAL);
        cudaFuncSetAttribute(qk_mma,  cudaFuncAttributeMaxDynamicSharedMemorySize, SMEM_TOTAL);
        cudaFuncSetAttribute(pv_mma,  cudaFuncAttributeMaxDynamicSharedMemorySize, SMEM_TOTAL);
        attr_done = true;
    }

    u16* wh0; u16* wl0;
    cudaGetSymbolAddress((void**)&wh0, g_wh);
    cudaGetSymbolAddress((void**)&wl0, g_wl);
    u16* xh; u16* xl;
    cudaGetSymbolAddress((void**)&xh, g_xh);
    cudaGetSymbolAddress((void**)&xl, g_xl);

    dim3 blk(256);
    cvt_split<<<2048, blk>>>(x,  xh, xl, (NXT * NCH) / 4);
    cvt_split<<<512,  blk>>>(Wq, wh0,                     wl0,                     (NCH * NCH) / 4);
    cvt_split<<<512,  blk>>>(Wk, wh0 + (size_t)NCH*NCH,   wl0 + (size_t)NCH*NCH,   (NCH * NCH) / 4);
    cvt_split<<<512,  blk>>>(Wv, wh0 + (size_t)2*NCH*NCH, wl0 + (size_t)2*NCH*NCH, (NCH * NCH) / 4);

    qkv_mma<<<dim3(64, 8, 3), blk, SMEM_TOTAL>>>(0);
    qk_mma<<<dim3(16, 16, NB), blk, SMEM_TOTAL>>>(0);
    softmax_causal<<<dim3(NT, NB), blk>>>(1.0f / 32.0f);   // 1024^-0.5
    pv_mma<<<dim3(8, 16, NB), blk, SMEM_TOTAL>>>(out);
}

// round 6
// speedup vs baseline: 1.0889x; 1.0504x over previous
#include <cuda_runtime.h>
#include <cstdint>
#include <math.h>

// ---------------------------------------------------------------------------
// Attention_3856880632117 — mma.sync bf16 3-term split, cp.async 3-stage ring,
// 512-thread CTAs (16 warps, 4x4 warp grid, 32x32 warp tile on 128x128 CTA tile).
// ptxas target is plain sm_103 (no 'a'): tcgen05 unavailable; tensor cores via
// baseline mma.sync.m16n8k16.bf16 + ldmatrix + cp.async.
//
// Operands pre-split into bf16 (hi, lo) exactly once (cvt_split / epilogues /
// softmax). GEMM hot loop: cp.async -> ldmatrix -> HMMA only.
// C = A*B^T; fp32 accuracy via C += Ah*Bh + Ah*Bl + Al*Bh.
// ---------------------------------------------------------------------------

#define NB 4
#define NT 2048
#define NCH 1024
#define NXT (NB * NT)      // 8192
#define NTHR 512

typedef unsigned short u16;

// Scratch (allocation-free rule: __device__ globals).
__device__ u16  g_xh [(size_t)NXT * NCH];
__device__ u16  g_xl [(size_t)NXT * NCH];
__device__ u16  g_wh [3][(size_t)NCH * NCH];
__device__ u16  g_wl [3][(size_t)NCH * NCH];
__device__ u16  g_qh [(size_t)NXT * NCH];
__device__ u16  g_ql [(size_t)NXT * NCH];
__device__ u16  g_kh [(size_t)NXT * NCH];
__device__ u16  g_kl [(size_t)NXT * NCH];
__device__ u16  g_vth[(size_t)NCH * NXT];    // V^T: [c][b*T + t]
__device__ u16  g_vtl[(size_t)NCH * NXT];
__device__ float g_s [(size_t)NB * NT * NT]; // scores (fp32 for softmax)
__device__ u16  g_sh [(size_t)NB * NT * NT]; // probs hi
__device__ u16  g_sl [(size_t)NB * NT * NT]; // probs lo

// ---------------- primitives ------------------------------------------------
__device__ __forceinline__ void ldsm4(uint32_t* r, uint32_t addr) {
    asm volatile("ldmatrix.sync.aligned.m8n8.x4.shared.b16 {%0,%1,%2,%3}, [%4];"
                 : "=r"(r[0]), "=r"(r[1]), "=r"(r[2]), "=r"(r[3]) : "r"(addr));
}
__device__ __forceinline__ void mma_bf16(float* c, const uint32_t* a, const uint32_t* b) {
    asm volatile(
        "mma.sync.aligned.m16n8k16.row.col.f32.bf16.bf16.f32 "
        "{%0,%1,%2,%3},{%4,%5,%6,%7},{%8,%9},{%0,%1,%2,%3};"
        : "+f"(c[0]), "+f"(c[1]), "+f"(c[2]), "+f"(c[3])
        : "r"(a[0]), "r"(a[1]), "r"(a[2]), "r"(a[3]), "r"(b[0]), "r"(b[1]));
}
__device__ __forceinline__ uint32_t smem_u32(const void* p) {
    uint32_t a;
    asm("{ .reg .u64 t; cvta.to.shared.u64 t, %1; cvt.u32.u64 %0, t; }"
        : "=r"(a) : "l"(p));
    return a;
}
__device__ __forceinline__ uint32_t pack2(float a, float b) {
    uint32_t r;
    asm("cvt.rn.bf16x2.f32 %0, %1, %2;" : "=r"(r) : "f"(a), "f"(b));
    return r;
}
__device__ __forceinline__ void cp16(uint32_t dst, const void* src) {
    asm volatile("cp.async.cg.shared.global [%0], [%1], 16;" :: "r"(dst), "l"(src));
}
#define CP_COMMIT() asm volatile("cp.async.commit_group;" ::: "memory")
#define CP_WAIT(n)  asm volatile("cp.async.wait_group %0;" :: "n"(n) : "memory")

// ---------------------------------------------------------------------------
// SMEM: per stage, 4 regions (Ah|Al|Bh|Bl), 128 rows x 64B payload, 80B pitch
// (conflict-free ldmatrix). 3 stages.
// ---------------------------------------------------------------------------
#define PITCHB     80
#define REGION     10240
#define STAGE_B    40960
#define NSTAGE     3
#define SMEM_TOTAL (NSTAGE * STAGE_B)

// Core: accumulate 128x128 tile over nch K-chunks of 32.
// Warp grid 4x4: warp (wm, wn) owns rows [wm*32, +32), cols [wn*32, +32).
__device__ __forceinline__ void mma_core(
    const u16* __restrict__ Ah, const u16* __restrict__ Al, int lda,
    const u16* __restrict__ Bh, const u16* __restrict__ Bl, int ldb,
    int nch, float (&acc)[2][4][4])
{
    extern __shared__ char smraw[];
    const uint32_t smu = smem_u32(smraw);

    const int tid  = threadIdx.x;
    const int lane = tid & 31;
    const int wid  = tid >> 5;
    const int wm   = wid >> 2;   // 0..3
    const int wn   = wid & 3;    // 0..3

    const uint32_t aRowByte = (uint32_t)(lane & 15) * PITCHB + (uint32_t)(lane >> 4) * 16;
    const uint32_t bRowByte = (uint32_t)(((lane >> 4) << 3) + (lane & 7)) * PITCHB
                            + (uint32_t)((lane >> 3) & 1) * 16;

    const int row0 = tid >> 2;          // 0..127: one row per thread
    const int seg  = tid & 3;           // 16B segment within 64B payload

    auto load_chunk = [&](int kt, int buf) {
        const int kb = kt * 32;
        const uint32_t sb = smu + (uint32_t)buf * STAGE_B;
        const uint32_t d = sb + (uint32_t)row0 * PITCHB + (uint32_t)seg * 16;
        const size_t ao = (size_t)row0 * lda + kb + seg * 8;
        const size_t bo = (size_t)row0 * ldb + kb + seg * 8;
        cp16(d,              Ah + ao);
        cp16(d + REGION,     Al + ao);
        cp16(d + 2 * REGION, Bh + bo);
        cp16(d + 3 * REGION, Bl + bo);
        CP_COMMIT();
    };

    auto mma_chunk = [&](int buf) {
        const uint32_t sbase = smu + (uint32_t)buf * STAGE_B;
        #pragma unroll
        for (int sk = 0; sk < 2; ++sk) {
            uint32_t ah[2][4], al[2][4], bh[4][2], bl[4][2];
            const uint32_t aBase = sbase + (uint32_t)(wm * 32) * PITCHB + aRowByte
                                 + (uint32_t)sk * 32;
            #pragma unroll
            for (int mf = 0; mf < 2; ++mf) {
                ldsm4(ah[mf], aBase + (uint32_t)mf * (16 * PITCHB));
                ldsm4(al[mf], aBase + (uint32_t)mf * (16 * PITCHB) + REGION);
            }
            const uint32_t bBase = sbase + 2 * REGION + (uint32_t)(wn * 32) * PITCHB
                                 + bRowByte + (uint32_t)sk * 32;
            #pragma unroll
            for (int p = 0; p < 2; ++p) {
                uint32_t t[4];
                ldsm4(t, bBase + (uint32_t)p * (16 * PITCHB));
                bh[2 * p][0] = t[0]; bh[2 * p][1] = t[1];
                bh[2 * p + 1][0] = t[2]; bh[2 * p + 1][1] = t[3];
                ldsm4(t, bBase + (uint32_t)p * (16 * PITCHB) + REGION);
                bl[2 * p][0] = t[0]; bl[2 * p][1] = t[1];
                bl[2 * p + 1][0] = t[2]; bl[2 * p + 1][1] = t[3];
            }
            #pragma unroll
            for (int mf = 0; mf < 2; ++mf)
                #pragma unroll
                for (int nf = 0; nf < 4; ++nf)
                    mma_bf16(acc[mf][nf], ah[mf], bh[nf]);
            #pragma unroll
            for (int mf = 0; mf < 2; ++mf)
                #pragma unroll
                for (int nf = 0; nf < 4; ++nf)
                    mma_bf16(acc[mf][nf], ah[mf], bl[nf]);
            #pragma unroll
            for (int mf = 0; mf < 2; ++mf)
                #pragma unroll
                for (int nf = 0; nf < 4; ++nf)
                    mma_bf16(acc[mf][nf], al[mf], bh[nf]);
        }
    };

    // 3-stage ring, one barrier per chunk, prefetch distance 2.
    load_chunk(0, 0);
    if (nch > 1) load_chunk(1, 1);
    for (int kt = 0; kt < nch; ++kt) {
        if (kt + 1 < nch) { CP_WAIT(1); } else { CP_WAIT(0); }
        __syncthreads();                 // chunk kt visible; all warps past mma(kt-1)
        mma_chunk(kt % NSTAGE);
        if (kt + 2 < nch)                // buf (kt+2)%3 consumed at iter kt-1
            load_chunk(kt + 2, (kt + 2) % NSTAGE);
    }
}

// fp32 epilogue
__device__ __forceinline__ void epi_f32(float (&acc)[2][4][4],
                                        float* __restrict__ Ct, int ldc)
{
    const int lane = threadIdx.x & 31, wid = threadIdx.x >> 5;
    const int wm = wid >> 2, wn = wid & 3;
    #pragma unroll
    for (int mf = 0; mf < 2; ++mf)
        #pragma unroll
        for (int nf = 0; nf < 4; ++nf) {
            int row = wm * 32 + mf * 16 + (lane >> 2);
            int col = wn * 32 + nf * 8 + (lane & 3) * 2;
            *reinterpret_cast<float2*>(Ct + (size_t)row * ldc + col) =
                make_float2(acc[mf][nf][0], acc[mf][nf][1]);
            *reinterpret_cast<float2*>(Ct + (size_t)(row + 8) * ldc + col) =
                make_float2(acc[mf][nf][2], acc[mf][nf][3]);
        }
}

// bf16 hi/lo epilogue
__device__ __forceinline__ void epi_bf16(float (&acc)[2][4][4],
                                         u16* __restrict__ Chi,
                                         u16* __restrict__ Clo, int ldc)
{
    const int lane = threadIdx.x & 31, wid = threadIdx.x >> 5;
    const int wm = wid >> 2, wn = wid & 3;
    #pragma unroll
    for (int mf = 0; mf < 2; ++mf)
        #pragma unroll
        for (int nf = 0; nf < 4; ++nf) {
            int row = wm * 32 + mf * 16 + (lane >> 2);
            int col = wn * 32 + nf * 8 + (lane & 3) * 2;
            float c0 = acc[mf][nf][0], c1 = acc[mf][nf][1];
            float c2 = acc[mf][nf][2], c3 = acc[mf][nf][3];
            uint32_t h01 = pack2(c1, c0);
            uint32_t h23 = pack2(c3, c2);
            float f0 = __uint_as_float(h01 << 16);
            float f1 = __uint_as_float(h01 & 0xFFFF0000u);
            float f2 = __uint_as_float(h23 << 16);
            float f3 = __uint_as_float(h23 & 0xFFFF0000u);
            uint32_t l01 = pack2(c1 - f1, c0 - f0);
            uint32_t l23 = pack2(c3 - f3, c2 - f2);
            *reinterpret_cast<uint32_t*>(Chi + (size_t)row * ldc + col) = h01;
            *reinterpret_cast<uint32_t*>(Clo + (size_t)row * ldc + col) = l01;
            *reinterpret_cast<uint32_t*>(Chi + (size_t)(row + 8) * ldc + col) = h23;
            *reinterpret_cast<uint32_t*>(Clo + (size_t)(row + 8) * ldc + col) = l23;
        }
}

// cvt_split: fp32 -> (bf16 hi, bf16 lo)
__global__ __launch_bounds__(256)
void cvt_split(const float* __restrict__ src, u16* __restrict__ hi,
               u16* __restrict__ lo, int n4)
{
    for (int i = blockIdx.x * 256 + threadIdx.x; i < n4; i += gridDim.x * 256) {
        float4 v = reinterpret_cast<const float4*>(src)[i];
        uint32_t h01 = pack2(v.y, v.x);
        uint32_t h23 = pack2(v.w, v.z);
        float fx = __uint_as_float(h01 << 16);
        float fy = __uint_as_float(h01 & 0xFFFF0000u);
        float fz = __uint_as_float(h23 << 16);
        float fw = __uint_as_float(h23 & 0xFFFF0000u);
        uint32_t l01 = pack2(v.y - fy, v.x - fx);
        uint32_t l23 = pack2(v.w - fw, v.z - fz);
        reinterpret_cast<uint2*>(hi)[i] = make_uint2(h01, h23);
        reinterpret_cast<uint2*>(lo)[i] = make_uint2(l01, l23);
    }
}

// Stage 1: QKV. grid=(64,8,3), 512 thr.
__global__ __launch_bounds__(NTHR)
void qkv_mma(int dummy)
{
    const int bx = blockIdx.x, by = blockIdx.y, z = blockIdx.z;
    float acc[2][4][4];
    #pragma unroll
    for (int a = 0; a < 2; ++a)
        #pragma unroll
        for (int b = 0; b < 4; ++b)
            #pragma unroll
            for (int c = 0; c < 4; ++c) acc[a][b][c] = 0.0f;

    if (z < 2) {
        mma_core(g_xh + (size_t)bx * 128 * NCH, g_xl + (size_t)bx * 128 * NCH, NCH,
                 g_wh[z] + (size_t)by * 128 * NCH, g_wl[z] + (size_t)by * 128 * NCH, NCH,
                 NCH / 32, acc);
        u16* oh = (z == 0) ? g_qh : g_kh;
        u16* ol = (z == 0) ? g_ql : g_kl;
        epi_bf16(acc, oh + (size_t)bx * 128 * NCH + by * 128,
                      ol + (size_t)bx * 128 * NCH + by * 128, NCH);
    } else {
        mma_core(g_wh[2] + (size_t)by * 128 * NCH, g_wl[2] + (size_t)by * 128 * NCH, NCH,
                 g_xh + (size_t)bx * 128 * NCH, g_xl + (size_t)bx * 128 * NCH, NCH,
                 NCH / 32, acc);
        epi_bf16(acc, g_vth + (size_t)by * 128 * NXT + bx * 128,
                      g_vtl + (size_t)by * 128 * NXT + bx * 128, NXT);
    }
}

// Stage 2: S = Q K^T, lower-triangular tiles. grid=(16,16,NB), 512 thr.
__global__ __launch_bounds__(NTHR)
void qk_mma(int dummy)
{
    if (blockIdx.x > blockIdx.y) return;
    const int b = blockIdx.z;
    const size_t qo = (size_t)b * NT * NCH + (size_t)blockIdx.y * 128 * NCH;
    const size_t ko = (size_t)b * NT * NCH + (size_t)blockIdx.x * 128 * NCH;
    float acc[2][4][4];
    #pragma unroll
    for (int a = 0; a < 2; ++a)
        #pragma unroll
        for (int bb = 0; bb < 4; ++bb)
            #pragma unroll
            for (int c = 0; c < 4; ++c) acc[a][bb][c] = 0.0f;
    mma_core(g_qh + qo, g_ql + qo, NCH, g_kh + ko, g_kl + ko, NCH, NCH / 32, acc);
    epi_f32(acc, g_s + (size_t)b * NT * NT + (size_t)blockIdx.y * 128 * NT
                     + blockIdx.x * 128, NT);
}

// Stage 3: causal softmax (scale fused); writes P as bf16 hi/lo, zero-padded.
__global__ __launch_bounds__(256)
void softmax_causal(float scale)
{
    const int i = blockIdx.x;
    const size_t ro = ((size_t)blockIdx.y * NT + i) * NT;
    float* row = g_s + ro;
    const int len = i + 1;
    const int tid = threadIdx.x;
    const int lane = tid & 31, warp = tid >> 5;

    __shared__ float sh[8];
    __shared__ float s_bcast;

    float m = -INFINITY;
    for (int j = tid; j < len; j += 256) m = fmaxf(m, row[j]);
    #pragma unroll
    for (int o = 16; o > 0; o >>= 1) m = fmaxf(m, __shfl_xor_sync(0xffffffffu, m, o));
    if (lane == 0) sh[warp] = m;
    __syncthreads();
    if (tid < 32) {
        float v = (lane < 8) ? sh[lane] : -INFINITY;
        #pragma unroll
        for (int o = 4; o > 0; o >>= 1) v = fmaxf(v, __shfl_xor_sync(0xffffffffu, v, o));
        if (lane == 0) s_bcast = v;
    }
    __syncthreads();
    m = s_bcast;
    __syncthreads();

    float s = 0.0f;
    for (int j = tid; j < len; j += 256) {
        float e = __expf((row[j] - m) * scale);
        row[j] = e;
        s += e;
    }
    #pragma unroll
    for (int o = 16; o > 0; o >>= 1) s += __shfl_xor_sync(0xffffffffu, s, o);
    if (lane == 0) sh[warp] = s;
    __syncthreads();
    if (tid < 32) {
        float v = (lane < 8) ? sh[lane] : 0.0f;
        #pragma unroll
        for (int o = 4; o > 0; o >>= 1) v += __shfl_xor_sync(0xffffffffu, v, o);
        if (lane == 0) s_bcast = v;
    }
    __syncthreads();
    const float inv = 1.0f / s_bcast;

    const int jend = ((i >> 7) + 1) << 7;   // pad to 128 boundary
    for (int j2 = tid * 2; j2 < jend; j2 += 512) {
        float p0 = (j2     < len) ? row[j2]     * inv : 0.0f;
        float p1 = (j2 + 1 < len) ? row[j2 + 1] * inv : 0.0f;
        uint32_t h = pack2(p1, p0);
        float f0 = __uint_as_float(h << 16);
        float f1 = __uint_as_float(h & 0xFFFF0000u);
        uint32_t l = pack2(p1 - f1, p0 - f0);
        *reinterpret_cast<uint32_t*>(g_sh + ro + j2) = h;
        *reinterpret_cast<uint32_t*>(g_sl + ro + j2) = l;
    }
}

// Stage 4: out = P vt^T, k-extent clipped. grid=(8,16,NB), 512 thr.
__global__ __launch_bounds__(NTHR)
void pv_mma(float* __restrict__ out)
{
    const int b = blockIdx.z, by = blockIdx.y, bx = blockIdx.x;
    const size_t so = (size_t)b * NT * NT + (size_t)by * 128 * NT;
    const size_t vo = (size_t)bx * 128 * NXT + (size_t)b * NT;
    float acc[2][4][4];
    #pragma unroll
    for (int a = 0; a < 2; ++a)
        #pragma unroll
        for (int bb = 0; bb < 4; ++bb)
            #pragma unroll
            for (int c = 0; c < 4; ++c) acc[a][bb][c] = 0.0f;
    mma_core(g_sh + so, g_sl + so, NT, g_vth + vo, g_vtl + vo, NXT,
             (by + 1) * 4, acc);
    epi_f32(acc, out + (size_t)b * NT * NCH + (size_t)by * 128 * NCH + bx * 128, NCH);
}

extern "C" void kernel_launch(void* const* d_in, const int* in_sizes, int n_in,
                              void* d_out, int out_size)
{
    const float* x  = (const float*)d_in[0];
    const float* Wq = (const float*)d_in[1];
    const float* Wk = (const float*)d_in[2];
    const float* Wv = (const float*)d_in[3];
    float* out = (float*)d_out;

    static bool attr_done = false;
    if (!attr_done) {
        cudaFuncSetAttribute(qkv_mma, cudaFuncAttributeMaxDynamicSharedMemorySize, SMEM_TOTAL);
        cudaFuncSetAttribute(qk_mma,  cudaFuncAttributeMaxDynamicSharedMemorySize, SMEM_TOTAL);
        cudaFuncSetAttribute(pv_mma,  cudaFuncAttributeMaxDynamicSharedMemorySize, SMEM_TOTAL);
        attr_done = true;
    }

    u16* wh0; u16* wl0;
    cudaGetSymbolAddress((void**)&wh0, g_wh);
    cudaGetSymbolAddress((void**)&wl0, g_wl);
    u16* xh; u16* xl;
    cudaGetSymbolAddress((void**)&xh, g_xh);
    cudaGetSymbolAddress((void**)&xl, g_xl);

    dim3 blk512(NTHR), blk256(256);
    cvt_split<<<2048, blk256>>>(x,  xh, xl, (NXT * NCH) / 4);
    cvt_split<<<512,  blk256>>>(Wq, wh0,                     wl0,                     (NCH * NCH) / 4);
    cvt_split<<<512,  blk256>>>(Wk, wh0 + (size_t)NCH*NCH,   wl0 + (size_t)NCH*NCH,   (NCH * NCH) / 4);
    cvt_split<<<512,  blk256>>>(Wv, wh0 + (size_t)2*NCH*NCH, wl0 + (size_t)2*NCH*NCH, (NCH * NCH) / 4);

    qkv_mma<<<dim3(64, 8, 3), blk512, SMEM_TOTAL>>>(0);
    qk_mma<<<dim3(16, 16, NB), blk512, SMEM_TOTAL>>>(0);
    softmax_causal<<<dim3(NT, NB), blk256>>>(1.0f / 32.0f);   // 1024^-0.5
    pv_mma<<<dim3(8, 16, NB), blk512, SMEM_TOTAL>>>(out);
}